// round 3
// baseline (speedup 1.0000x reference)
#include <cuda_runtime.h>
#include <cstdint>

#define H 128
#define MAXN 65536
#define MAXG 32768

// ---------------- device scratch (no allocs allowed) ----------------
__device__ float g_z[(size_t)MAXN * H];    // z = nf @ mm_w1_top   [N,128]
__device__ float g_S[(size_t)MAXG * H];    // sum of silu(pre)     [G,128]
__device__ int   g_cnt[MAXG];              // edges per target
__device__ float g_Wp[H * H];              // W' = em_w2 @ mm_w1_bot
__device__ float g_bpp[H];                 // b'' = mm_b1 + em_b2 @ mm_w1_bot
__device__ int   g_is64;                   // edge_index dtype flag
__device__ int   g_max_src;                // max src index (limits node MLP rows)

__device__ __forceinline__ float silu_f(float x) { return x / (1.f + __expf(-x)); }

// ---------------------------------------------------------------
// Generic fused layer on a 64x128 tile held in shared memory.
// 512 threads: cols j0=(t&31)*4, warp rg=t>>5 owns rows rg*4..rg*4+3.
// Inner loop: 1 LDS.128 (weights) + 4 broadcast LDS (x) per 16 FMA -> FMA bound.
// ---------------------------------------------------------------
template<bool ACT, bool HASBIAS, bool TOGLOBAL>
__device__ __forceinline__ void tile_layer(const float* __restrict__ W,
                                           const float* __restrict__ b,
                                           float* __restrict__ buf,
                                           float* __restrict__ gout, int t)
{
    const int j0 = (t & 31) << 2;
    const int r0 = (t >> 5) << 2;
    float acc[4][4];
#pragma unroll
    for (int i = 0; i < 4; i++)
#pragma unroll
        for (int c = 0; c < 4; c++)
            acc[i][c] = HASBIAS ? b[j0 + c] : 0.f;

#pragma unroll 8
    for (int k = 0; k < H; k++) {
        float4 w = *(const float4*)(W + k * H + j0);
        float x0 = buf[(r0 + 0) * H + k];
        float x1 = buf[(r0 + 1) * H + k];
        float x2 = buf[(r0 + 2) * H + k];
        float x3 = buf[(r0 + 3) * H + k];
        acc[0][0] += x0 * w.x; acc[0][1] += x0 * w.y; acc[0][2] += x0 * w.z; acc[0][3] += x0 * w.w;
        acc[1][0] += x1 * w.x; acc[1][1] += x1 * w.y; acc[1][2] += x1 * w.z; acc[1][3] += x1 * w.w;
        acc[2][0] += x2 * w.x; acc[2][1] += x2 * w.y; acc[2][2] += x2 * w.z; acc[2][3] += x2 * w.w;
        acc[3][0] += x3 * w.x; acc[3][1] += x3 * w.y; acc[3][2] += x3 * w.z; acc[3][3] += x3 * w.w;
    }

    if (TOGLOBAL) {
#pragma unroll
        for (int i = 0; i < 4; i++) {
            float4 v;
            v.x = ACT ? silu_f(acc[i][0]) : acc[i][0];
            v.y = ACT ? silu_f(acc[i][1]) : acc[i][1];
            v.z = ACT ? silu_f(acc[i][2]) : acc[i][2];
            v.w = ACT ? silu_f(acc[i][3]) : acc[i][3];
            *(float4*)(gout + (size_t)(r0 + i) * H + j0) = v;
        }
    } else {
        __syncwarp();  // our warp's pending reads of rows r0..r0+3 must drain
#pragma unroll
        for (int i = 0; i < 4; i++) {
            float4 v;
            v.x = ACT ? silu_f(acc[i][0]) : acc[i][0];
            v.y = ACT ? silu_f(acc[i][1]) : acc[i][1];
            v.z = ACT ? silu_f(acc[i][2]) : acc[i][2];
            v.w = ACT ? silu_f(acc[i][3]) : acc[i][3];
            *(float4*)(buf + (r0 + i) * H + j0) = v;
        }
        __syncthreads();
    }
}

// ---------------------------------------------------------------
// Probe: detect int64 vs int32 edge_index, and max(src).
// ---------------------------------------------------------------
__global__ void probe_kernel(const int* __restrict__ ei, int E)
{
    int is64 = 1;
#pragma unroll 1
    for (int i = 0; i < 64; i++)
        if (ei[2 * i + 1] != 0) { is64 = 0; break; }
    if (blockIdx.x == 0 && threadIdx.x == 0) g_is64 = is64;

    int tid = blockIdx.x * blockDim.x + threadIdx.x;
    int stride = gridDim.x * blockDim.x;
    int m = 0;
    for (int e = tid; e < E; e += stride) {
        int s = is64 ? ei[2 * (size_t)e] : ei[e];
        m = max(m, s);
    }
#pragma unroll
    for (int o = 16; o > 0; o >>= 1) m = max(m, __shfl_xor_sync(0xffffffffu, m, o));
    if ((threadIdx.x & 31) == 0) atomicMax(&g_max_src, m);
}

// ---------------------------------------------------------------
// Precompute W' = em_w2 @ mm_w1[128:,:]  and  b'' = mm_b1 + em_b2 @ mm_w1[128:,:]
// ---------------------------------------------------------------
__global__ void prep_kernel(const float* __restrict__ emw2,
                            const float* __restrict__ emb2,
                            const float* __restrict__ mmw1,
                            const float* __restrict__ mmb1)
{
    int j = threadIdx.x;
    if (blockIdx.x < 128) {
        int a = blockIdx.x;
        float s = 0.f;
        for (int bb = 0; bb < 128; bb++)
            s += emw2[a * 128 + bb] * mmw1[(128 + bb) * 128 + j];
        g_Wp[a * 128 + j] = s;
    } else {
        float s = mmb1[j];
        for (int bb = 0; bb < 128; bb++)
            s += emb2[bb] * mmw1[(128 + bb) * 128 + j];
        g_bpp[j] = s;
    }
}

// ---------------------------------------------------------------
// Node kernel: z = (MLP_node(x)) @ mm_w1_top for rows 0..max_src
// smem: 3 weights (192KB) + 2 biases + 64x128 tile = 230400 B
// ---------------------------------------------------------------
__global__ void __launch_bounds__(512, 1) node_kernel(
    const float* __restrict__ x,
    const float* __restrict__ w1, const float* __restrict__ b1g,
    const float* __restrict__ w2, const float* __restrict__ b2g,
    const float* __restrict__ w3, int Nrows)
{
    extern __shared__ float sh[];
    float* W1 = sh;
    float* W2 = sh + 16384;
    float* W3 = sh + 32768;
    float* B1 = sh + 49152;
    float* B2 = sh + 49280;
    float* buf = sh + 49408;
    int t = threadIdx.x;

    for (int i = t; i < 4096; i += 512) {
        ((float4*)W1)[i] = ((const float4*)w1)[i];
        ((float4*)W2)[i] = ((const float4*)w2)[i];
        ((float4*)W3)[i] = ((const float4*)w3)[i];
    }
    if (t < 128) { B1[t] = b1g[t]; B2[t] = b2g[t]; }
    __syncthreads();

    const int maxrow = g_max_src;
    const int ntiles = Nrows >> 6;
    for (int tile = blockIdx.x; tile < ntiles; tile += gridDim.x) {
        if ((tile << 6) > maxrow) continue;   // uniform across block
        const float4* xg = (const float4*)(x + (size_t)tile * 64 * H);
        for (int i = t; i < 2048; i += 512) ((float4*)buf)[i] = xg[i];
        __syncthreads();
        tile_layer<true,  true,  false>(W1, B1, buf, nullptr, t);              // silu
        tile_layer<false, true,  false>(W2, B2, buf, nullptr, t);              // linear
        tile_layer<false, false, true >(W3, nullptr, buf,
                                        g_z + (size_t)tile * 64 * H, t);       // -> z
        __syncthreads();
    }
}

// ---------------------------------------------------------------
// Edge kernel: per edge  pre = z[src] + silu(attr@em_w1+em_b1) @ W' + b''
//              scatter   red.v4 S[tgt] += silu(pre);  cnt[tgt]++
// 256 threads, 16 edges/tile. smem = 78464 B -> 2 blocks/SM.
// ---------------------------------------------------------------
__global__ void __launch_bounds__(256, 2) edge_kernel(
    const int* __restrict__ ei,
    const float* __restrict__ node_pos,
    const float* __restrict__ grid_pos,
    const float* __restrict__ ew1g,
    const float* __restrict__ eb1g,
    int E)
{
    extern __shared__ float sh[];
    float* Wp   = sh;                  // 16384
    float* EW1  = sh + 16384;          // 768
    float* EB1  = sh + 17152;          // 128
    float* BPP  = sh + 17280;          // 128
    float* hbuf = sh + 17408;          // 16*128 = 2048
    float* attr = sh + 19456;          // 16*6 (padded region to 19584)
    int*   ssrc = (int*)(sh + 19584);  // 16
    int*   stgt = (int*)(sh + 19600);  // 16  -> total 19616 floats = 78464 B
    int t = threadIdx.x;

    for (int i = t; i < 4096; i += 256) ((float4*)Wp)[i] = ((const float4*)g_Wp)[i];
    for (int i = t; i < 768; i += 256) EW1[i] = ew1g[i];
    if (t < 128) { EB1[t] = eb1g[t]; BPP[t] = g_bpp[t]; }
    __syncthreads();

    const int is64 = g_is64;
    const int ntiles = (E + 15) >> 4;
    const int jj  = t & 127;
    const int hrb = (t >> 7) * 8;        // h rows: 0..7 or 8..15
    const int j0  = (t & 31) << 2;       // main cols
    const int r0  = (t >> 5) << 1;       // main rows: 2 per warp

    for (int tile = blockIdx.x; tile < ntiles; tile += gridDim.x) {
        const int e0 = tile << 4;
        if (t < 32) {
            int r = t & 15;
            int e = e0 + r; if (e >= E) e = E - 1;
            if (t < 16) ssrc[r] = is64 ? ei[2 * (size_t)e] : ei[e];
            else        stgt[r] = is64 ? ei[2 * ((size_t)E + e)] : ei[(size_t)E + e];
        }
        __syncthreads();
        if (t < 96) {
            int r = t / 6, k = t - r * 6;
            attr[r * 6 + k] = (k < 3) ? node_pos[(size_t)ssrc[r] * 3 + k]
                                      : grid_pos[(size_t)stgt[r] * 3 + (k - 3)];
        }
        __syncthreads();

        // h_e = silu(attr @ em_w1 + em_b1): 6-wide input
#pragma unroll
        for (int i = 0; i < 8; i++) {
            int r = hrb + i;
            float v = EB1[jj];
#pragma unroll
            for (int k = 0; k < 6; k++) v += attr[r * 6 + k] * EW1[k * H + jj];
            hbuf[r * H + jj] = silu_f(v);
        }
        __syncthreads();

        // pre = z[src] + b'' + h_e @ W'
        float acc[2][4];
        {
            const float4 z0 = *(const float4*)(g_z + (size_t)ssrc[r0]     * H + j0);
            const float4 z1 = *(const float4*)(g_z + (size_t)ssrc[r0 + 1] * H + j0);
            acc[0][0] = z0.x + BPP[j0];     acc[0][1] = z0.y + BPP[j0 + 1];
            acc[0][2] = z0.z + BPP[j0 + 2]; acc[0][3] = z0.w + BPP[j0 + 3];
            acc[1][0] = z1.x + BPP[j0];     acc[1][1] = z1.y + BPP[j0 + 1];
            acc[1][2] = z1.z + BPP[j0 + 2]; acc[1][3] = z1.w + BPP[j0 + 3];
        }
#pragma unroll 8
        for (int k = 0; k < H; k++) {
            float4 w = *(const float4*)(Wp + k * H + j0);
            float h0 = hbuf[r0 * H + k];
            float h1 = hbuf[(r0 + 1) * H + k];
            acc[0][0] += h0 * w.x; acc[0][1] += h0 * w.y; acc[0][2] += h0 * w.z; acc[0][3] += h0 * w.w;
            acc[1][0] += h1 * w.x; acc[1][1] += h1 * w.y; acc[1][2] += h1 * w.z; acc[1][3] += h1 * w.w;
        }

        // scatter silu(pre) with vector reductions
#pragma unroll
        for (int i = 0; i < 2; i++) {
            int e = e0 + r0 + i;
            if (e < E) {
                float a = silu_f(acc[i][0]);
                float b = silu_f(acc[i][1]);
                float c = silu_f(acc[i][2]);
                float d = silu_f(acc[i][3]);
                float* p = g_S + (size_t)stgt[r0 + i] * H + j0;
                asm volatile("red.global.add.v4.f32 [%0], {%1,%2,%3,%4};"
                             :: "l"(p), "f"(a), "f"(b), "f"(c), "f"(d) : "memory");
            }
        }
        if (t < 16 && (e0 + t) < E) atomicAdd(&g_cnt[stgt[t]], 1);
        __syncthreads();
    }
}

// ---------------------------------------------------------------
// Grid kernel: A = S/max(c,1); agg = A@mm_w2 + [c>0]*mm_b2; out = MLP_update(agg)
// smem = 231424 B
// ---------------------------------------------------------------
__global__ void __launch_bounds__(512, 1) grid_kernel(
    const float* __restrict__ w1, const float* __restrict__ b1g,
    const float* __restrict__ w2, const float* __restrict__ b2g,
    const float* __restrict__ w3, const float* __restrict__ b3g,
    float* __restrict__ out, int Grows)
{
    extern __shared__ float sh[];
    float* W1 = sh;
    float* W2 = sh + 16384;
    float* W3 = sh + 32768;
    float* B1 = sh + 49152;
    float* B2 = sh + 49280;
    float* B3 = sh + 49408;
    float* RS = sh + 49536;   // per-row 1/max(c,1)
    float* RM = sh + 49600;   // per-row [c>0]
    float* buf = sh + 49664;
    int t = threadIdx.x;

    for (int i = t; i < 4096; i += 512) {
        ((float4*)W1)[i] = ((const float4*)w1)[i];
        ((float4*)W2)[i] = ((const float4*)w2)[i];
        ((float4*)W3)[i] = ((const float4*)w3)[i];
    }
    if (t < 128) { B1[t] = b1g[t]; B2[t] = b2g[t]; B3[t] = b3g[t]; }
    __syncthreads();

    const int ntiles = Grows >> 6;
    const int j0 = (t & 31) << 2;
    const int r0 = (t >> 5) << 2;

    for (int tile = blockIdx.x; tile < ntiles; tile += gridDim.x) {
        const int base = tile << 6;
        if (t < 64) {
            int c = g_cnt[base + t];
            RS[t] = 1.f / (float)max(c, 1);
            RM[t] = (c > 0) ? 1.f : 0.f;
        }
        __syncthreads();
        for (int i = t; i < 2048; i += 512) {
            float4 v = ((const float4*)(g_S + (size_t)base * H))[i];
            float s = RS[i >> 5];
            v.x *= s; v.y *= s; v.z *= s; v.w *= s;
            ((float4*)buf)[i] = v;
        }
        __syncthreads();

        // layer1: A @ mm_w2 with per-row masked bias, no activation
        {
            float acc[4][4];
#pragma unroll
            for (int i = 0; i < 4; i++) {
                float m = RM[r0 + i];
#pragma unroll
                for (int c = 0; c < 4; c++) acc[i][c] = m * B1[j0 + c];
            }
#pragma unroll 8
            for (int k = 0; k < H; k++) {
                float4 w = *(const float4*)(W1 + k * H + j0);
                float x0 = buf[(r0 + 0) * H + k];
                float x1 = buf[(r0 + 1) * H + k];
                float x2 = buf[(r0 + 2) * H + k];
                float x3 = buf[(r0 + 3) * H + k];
                acc[0][0] += x0 * w.x; acc[0][1] += x0 * w.y; acc[0][2] += x0 * w.z; acc[0][3] += x0 * w.w;
                acc[1][0] += x1 * w.x; acc[1][1] += x1 * w.y; acc[1][2] += x1 * w.z; acc[1][3] += x1 * w.w;
                acc[2][0] += x2 * w.x; acc[2][1] += x2 * w.y; acc[2][2] += x2 * w.z; acc[2][3] += x2 * w.w;
                acc[3][0] += x3 * w.x; acc[3][1] += x3 * w.y; acc[3][2] += x3 * w.z; acc[3][3] += x3 * w.w;
            }
            __syncwarp();
#pragma unroll
            for (int i = 0; i < 4; i++) {
                float4 v = { acc[i][0], acc[i][1], acc[i][2], acc[i][3] };
                *(float4*)(buf + (r0 + i) * H + j0) = v;
            }
            __syncthreads();
        }

        tile_layer<true,  true, false>(W2, B2, buf, nullptr, t);                    // silu
        tile_layer<false, true, true >(W3, B3, buf, out + (size_t)base * H, t);     // -> out
        __syncthreads();
    }
}

// ---------------------------------------------------------------
extern "C" void kernel_launch(void* const* d_in, const int* in_sizes, int n_in,
                              void* d_out, int out_size)
{
    const float* node_features = (const float*)d_in[0];
    const float* node_pos = (const float*)d_in[1];
    const float* grid_pos = (const float*)d_in[2];
    const int*   eidx     = (const int*)d_in[3];
    const float* nm_w1 = (const float*)d_in[4],  *nm_b1 = (const float*)d_in[5];
    const float* nm_w2 = (const float*)d_in[6],  *nm_b2 = (const float*)d_in[7];
    const float* em_w1 = (const float*)d_in[8],  *em_b1 = (const float*)d_in[9];
    const float* em_w2 = (const float*)d_in[10], *em_b2 = (const float*)d_in[11];
    const float* mm_w1 = (const float*)d_in[12], *mm_b1 = (const float*)d_in[13];
    const float* mm_w2 = (const float*)d_in[14], *mm_b2 = (const float*)d_in[15];
    const float* um_w1 = (const float*)d_in[16], *um_b1 = (const float*)d_in[17];
    const float* um_w2 = (const float*)d_in[18], *um_b2 = (const float*)d_in[19];
    float* out = (float*)d_out;

    const int Nn = in_sizes[0] / H;   // 65536
    const int Gg = in_sizes[2] / 3;   // 32768
    const int Ee = in_sizes[3] / 2;   // 600000 (elements = 2E for int32 or int64)

    int nSM = 148;
    cudaDeviceGetAttribute(&nSM, cudaDevAttrMultiProcessorCount, 0);

    void *pS = nullptr, *pC = nullptr, *pM = nullptr;
    cudaGetSymbolAddress(&pS, g_S);
    cudaGetSymbolAddress(&pC, g_cnt);
    cudaGetSymbolAddress(&pM, g_max_src);
    cudaMemsetAsync(pS, 0, (size_t)Gg * H * sizeof(float));
    cudaMemsetAsync(pC, 0, (size_t)Gg * sizeof(int));
    cudaMemsetAsync(pM, 0, sizeof(int));

    probe_kernel<<<256, 256>>>(eidx, Ee);
    prep_kernel<<<129, 128>>>(em_w2, em_b2, mm_w1, mm_b1);

    cudaFuncSetAttribute(node_kernel, cudaFuncAttributeMaxDynamicSharedMemorySize, 230400);
    cudaFuncSetAttribute(edge_kernel, cudaFuncAttributeMaxDynamicSharedMemorySize, 78464);
    cudaFuncSetAttribute(grid_kernel, cudaFuncAttributeMaxDynamicSharedMemorySize, 231424);

    node_kernel<<<nSM, 512, 230400>>>(node_features, nm_w1, nm_b1, nm_w2, nm_b2, mm_w1, Nn);
    edge_kernel<<<2 * nSM, 256, 78464>>>(eidx, node_pos, grid_pos, em_w1, em_b1, Ee);
    grid_kernel<<<nSM, 512, 231424>>>(mm_w2, mm_b2, um_w1, um_b1, um_w2, um_b2, out, Gg);
}

// round 11
// speedup vs baseline: 1.3945x; 1.3945x over previous
#include <cuda_runtime.h>
#include <cstdint>

#define H 128
#define MAXN 65536
#define MAXG 32768

// ---------------- device scratch (no allocs allowed) ----------------
__device__ float g_z[(size_t)MAXN * H];    // z = nf @ mm_w1_top   [N,128]
__device__ float g_S[(size_t)MAXG * H];    // sum of silu(pre)     [G,128]
__device__ int   g_cnt[MAXG];              // edges per target
__device__ float g_Wp[H * H];              // W' = em_w2 @ mm_w1_bot
__device__ float g_bpp[H];                 // b'' = mm_b1 + em_b2 @ mm_w1_bot
__device__ int   g_is64;                   // edge_index dtype flag
__device__ int   g_max_src;                // max src index (limits node MLP rows)

__device__ __forceinline__ float silu_f(float x) { return x / (1.f + __expf(-x)); }

// ---------------------------------------------------------------
// Generic fused layer on a 64x128 tile held in shared memory.
// 512 threads: cols j0=(t&31)*4, warp rg=t>>5 owns rows rg*4..rg*4+3.
// ---------------------------------------------------------------
template<bool ACT, bool HASBIAS, bool TOGLOBAL>
__device__ __forceinline__ void tile_layer(const float* __restrict__ W,
                                           const float* __restrict__ b,
                                           float* __restrict__ buf,
                                           float* __restrict__ gout, int t)
{
    const int j0 = (t & 31) << 2;
    const int r0 = (t >> 5) << 2;
    float acc[4][4];
#pragma unroll
    for (int i = 0; i < 4; i++)
#pragma unroll
        for (int c = 0; c < 4; c++)
            acc[i][c] = HASBIAS ? b[j0 + c] : 0.f;

#pragma unroll 8
    for (int k = 0; k < H; k++) {
        float4 w = *(const float4*)(W + k * H + j0);
        float x0 = buf[(r0 + 0) * H + k];
        float x1 = buf[(r0 + 1) * H + k];
        float x2 = buf[(r0 + 2) * H + k];
        float x3 = buf[(r0 + 3) * H + k];
        acc[0][0] += x0 * w.x; acc[0][1] += x0 * w.y; acc[0][2] += x0 * w.z; acc[0][3] += x0 * w.w;
        acc[1][0] += x1 * w.x; acc[1][1] += x1 * w.y; acc[1][2] += x1 * w.z; acc[1][3] += x1 * w.w;
        acc[2][0] += x2 * w.x; acc[2][1] += x2 * w.y; acc[2][2] += x2 * w.z; acc[2][3] += x2 * w.w;
        acc[3][0] += x3 * w.x; acc[3][1] += x3 * w.y; acc[3][2] += x3 * w.z; acc[3][3] += x3 * w.w;
    }

    if (TOGLOBAL) {
#pragma unroll
        for (int i = 0; i < 4; i++) {
            float4 v;
            v.x = ACT ? silu_f(acc[i][0]) : acc[i][0];
            v.y = ACT ? silu_f(acc[i][1]) : acc[i][1];
            v.z = ACT ? silu_f(acc[i][2]) : acc[i][2];
            v.w = ACT ? silu_f(acc[i][3]) : acc[i][3];
            *(float4*)(gout + (size_t)(r0 + i) * H + j0) = v;
        }
    } else {
        __syncwarp();
#pragma unroll
        for (int i = 0; i < 4; i++) {
            float4 v;
            v.x = ACT ? silu_f(acc[i][0]) : acc[i][0];
            v.y = ACT ? silu_f(acc[i][1]) : acc[i][1];
            v.z = ACT ? silu_f(acc[i][2]) : acc[i][2];
            v.w = ACT ? silu_f(acc[i][3]) : acc[i][3];
            *(float4*)(buf + (r0 + i) * H + j0) = v;
        }
        __syncthreads();
    }
}

// ---------------------------------------------------------------
// Probe: detect int64 vs int32 edge_index, and max(src).
// ---------------------------------------------------------------
__global__ void probe_kernel(const int* __restrict__ ei, int E)
{
    int is64 = 1;
#pragma unroll 1
    for (int i = 0; i < 64; i++)
        if (ei[2 * i + 1] != 0) { is64 = 0; break; }
    if (blockIdx.x == 0 && threadIdx.x == 0) g_is64 = is64;

    int tid = blockIdx.x * blockDim.x + threadIdx.x;
    int stride = gridDim.x * blockDim.x;
    int m = 0;
    for (int e = tid; e < E; e += stride) {
        int s = is64 ? ei[2 * (size_t)e] : ei[e];
        m = max(m, s);
    }
#pragma unroll
    for (int o = 16; o > 0; o >>= 1) m = max(m, __shfl_xor_sync(0xffffffffu, m, o));
    if ((threadIdx.x & 31) == 0) atomicMax(&g_max_src, m);
}

// ---------------------------------------------------------------
// Precompute W' = em_w2 @ mm_w1[128:,:]  and  b'' = mm_b1 + em_b2 @ mm_w1[128:,:]
// ---------------------------------------------------------------
__global__ void prep_kernel(const float* __restrict__ emw2,
                            const float* __restrict__ emb2,
                            const float* __restrict__ mmw1,
                            const float* __restrict__ mmb1)
{
    int j = threadIdx.x;
    if (blockIdx.x < 128) {
        int a = blockIdx.x;
        float s = 0.f;
        for (int bb = 0; bb < 128; bb++)
            s += emw2[a * 128 + bb] * mmw1[(128 + bb) * 128 + j];
        g_Wp[a * 128 + j] = s;
    } else {
        float s = mmb1[j];
        for (int bb = 0; bb < 128; bb++)
            s += emb2[bb] * mmw1[(128 + bb) * 128 + j];
        g_bpp[j] = s;
    }
}

// ---------------------------------------------------------------
// Node kernel: z = (MLP_node(x)) @ mm_w1_top for rows 0..max_src
// ---------------------------------------------------------------
__global__ void __launch_bounds__(512, 1) node_kernel(
    const float* __restrict__ x,
    const float* __restrict__ w1, const float* __restrict__ b1g,
    const float* __restrict__ w2, const float* __restrict__ b2g,
    const float* __restrict__ w3, int Nrows)
{
    extern __shared__ float sh[];
    float* W1 = sh;
    float* W2 = sh + 16384;
    float* W3 = sh + 32768;
    float* B1 = sh + 49152;
    float* B2 = sh + 49280;
    float* buf = sh + 49408;
    int t = threadIdx.x;

    for (int i = t; i < 4096; i += 512) {
        ((float4*)W1)[i] = ((const float4*)w1)[i];
        ((float4*)W2)[i] = ((const float4*)w2)[i];
        ((float4*)W3)[i] = ((const float4*)w3)[i];
    }
    if (t < 128) { B1[t] = b1g[t]; B2[t] = b2g[t]; }
    __syncthreads();

    const int maxrow = g_max_src;
    const int ntiles = Nrows >> 6;
    for (int tile = blockIdx.x; tile < ntiles; tile += gridDim.x) {
        if ((tile << 6) > maxrow) continue;   // uniform across block
        const float4* xg = (const float4*)(x + (size_t)tile * 64 * H);
        for (int i = t; i < 2048; i += 512) ((float4*)buf)[i] = xg[i];
        __syncthreads();
        tile_layer<true,  true,  false>(W1, B1, buf, nullptr, t);
        tile_layer<false, true,  false>(W2, B2, buf, nullptr, t);
        tile_layer<false, false, true >(W3, nullptr, buf,
                                        g_z + (size_t)tile * 64 * H, t);
        __syncthreads();
    }
}

// ---------------------------------------------------------------
// Edge kernel v2.1: 64 edges/tile, 256 threads, acc[8][4] per thread.
// Per k: 1 LDS.128 (W' row slice) + 2 broadcast LDS.128 (hT) -> 32 FMAs.
// FIX vs v2: attr fill is a strided loop (384 entries > 256 threads).
// smem floats: Wp 16384 | hT 8192 | EW1 768 | EB1 128 | BPP 128
//              attr 384 | ssrc 64 | stgt 64  = 26112 f = 104448 B -> 2 blocks/SM
// ---------------------------------------------------------------
__global__ void __launch_bounds__(256, 2) edge_kernel(
    const int* __restrict__ ei,
    const float* __restrict__ node_pos,
    const float* __restrict__ grid_pos,
    const float* __restrict__ ew1g,
    const float* __restrict__ eb1g,
    int E)
{
    extern __shared__ float sh[];
    float* Wp   = sh;                   // 16384
    float* hT   = sh + 16384;           // 8192: [k][64 rows]
    float* EW1  = sh + 24576;           // 768
    float* EB1  = sh + 25344;           // 128
    float* BPP  = sh + 25472;           // 128
    float* attr = sh + 25600;           // 384
    int*   ssrc = (int*)(sh + 25984);   // 64
    int*   stgt = (int*)(sh + 26048);   // 64
    int t = threadIdx.x;

    for (int i = t; i < 4096; i += 256) ((float4*)Wp)[i] = ((const float4*)g_Wp)[i];
    for (int i = t; i < 768; i += 256) EW1[i] = ew1g[i];
    if (t < 128) { EB1[t] = eb1g[t]; BPP[t] = g_bpp[t]; }
    __syncthreads();

    const int is64 = g_is64;
    const int ntiles = (E + 63) >> 6;
    const int j0 = (t & 31) << 2;       // 4 output cols
    const int r0 = (t >> 5) << 3;       // 8 rows per warp
    const int hr = t & 63;              // h-phase row
    const int hkb = (t >> 6) << 5;      // h-phase col base (32 cols)

    for (int tile = blockIdx.x; tile < ntiles; tile += gridDim.x) {
        const int e0 = tile << 6;
        if (t < 128) {
            int r = t & 63;
            int e = e0 + r; if (e >= E) e = E - 1;
            if (t < 64) ssrc[r] = is64 ? ei[2 * (size_t)e] : ei[e];
            else        stgt[r] = is64 ? ei[2 * ((size_t)E + e)] : ei[(size_t)E + e];
        }
        __syncthreads();
        // FIX: 384 entries, 256 threads -> strided loop
        for (int i = t; i < 384; i += 256) {
            int r = i / 6, k = i - r * 6;
            attr[i] = (k < 3) ? node_pos[(size_t)ssrc[r] * 3 + k]
                              : grid_pos[(size_t)stgt[r] * 3 + (k - 3)];
        }
        __syncthreads();

        // h_e = silu(attr @ em_w1 + em_b1), stored transposed: hT[k][row]
        {
            float a0 = attr[hr * 6 + 0], a1 = attr[hr * 6 + 1], a2 = attr[hr * 6 + 2];
            float a3 = attr[hr * 6 + 3], a4 = attr[hr * 6 + 4], a5 = attr[hr * 6 + 5];
#pragma unroll 8
            for (int i = 0; i < 32; i++) {
                int k = hkb + i;
                float v = EB1[k]
                        + a0 * EW1[0 * H + k] + a1 * EW1[1 * H + k] + a2 * EW1[2 * H + k]
                        + a3 * EW1[3 * H + k] + a4 * EW1[4 * H + k] + a5 * EW1[5 * H + k];
                hT[k * 64 + hr] = silu_f(v);
            }
        }
        __syncthreads();

        // pre = z[src] + b'' + h_e @ W'  (acc[8][4] per thread)
        float acc[8][4];
#pragma unroll
        for (int i = 0; i < 8; i++) {
            const float4 z = *(const float4*)(g_z + (size_t)ssrc[r0 + i] * H + j0);
            acc[i][0] = z.x + BPP[j0];     acc[i][1] = z.y + BPP[j0 + 1];
            acc[i][2] = z.z + BPP[j0 + 2]; acc[i][3] = z.w + BPP[j0 + 3];
        }
#pragma unroll 8
        for (int k = 0; k < H; k++) {
            float4 w  = *(const float4*)(Wp + k * H + j0);
            float4 xa = *(const float4*)(hT + k * 64 + r0);       // rows r0..r0+3 (broadcast)
            float4 xb = *(const float4*)(hT + k * 64 + r0 + 4);   // rows r0+4..r0+7
            acc[0][0] += xa.x * w.x; acc[0][1] += xa.x * w.y; acc[0][2] += xa.x * w.z; acc[0][3] += xa.x * w.w;
            acc[1][0] += xa.y * w.x; acc[1][1] += xa.y * w.y; acc[1][2] += xa.y * w.z; acc[1][3] += xa.y * w.w;
            acc[2][0] += xa.z * w.x; acc[2][1] += xa.z * w.y; acc[2][2] += xa.z * w.z; acc[2][3] += xa.z * w.w;
            acc[3][0] += xa.w * w.x; acc[3][1] += xa.w * w.y; acc[3][2] += xa.w * w.z; acc[3][3] += xa.w * w.w;
            acc[4][0] += xb.x * w.x; acc[4][1] += xb.x * w.y; acc[4][2] += xb.x * w.z; acc[4][3] += xb.x * w.w;
            acc[5][0] += xb.y * w.x; acc[5][1] += xb.y * w.y; acc[5][2] += xb.y * w.z; acc[5][3] += xb.y * w.w;
            acc[6][0] += xb.z * w.x; acc[6][1] += xb.z * w.y; acc[6][2] += xb.z * w.z; acc[6][3] += xb.z * w.w;
            acc[7][0] += xb.w * w.x; acc[7][1] += xb.w * w.y; acc[7][2] += xb.w * w.z; acc[7][3] += xb.w * w.w;
        }

        // scatter silu(pre) with vector reductions
#pragma unroll
        for (int i = 0; i < 8; i++) {
            int e = e0 + r0 + i;
            if (e < E) {
                float a = silu_f(acc[i][0]);
                float b = silu_f(acc[i][1]);
                float c = silu_f(acc[i][2]);
                float d = silu_f(acc[i][3]);
                float* p = g_S + (size_t)stgt[r0 + i] * H + j0;
                asm volatile("red.global.add.v4.f32 [%0], {%1,%2,%3,%4};"
                             :: "l"(p), "f"(a), "f"(b), "f"(c), "f"(d) : "memory");
            }
        }
        if (t < 64 && (e0 + t) < E) atomicAdd(&g_cnt[stgt[t]], 1);
        __syncthreads();
    }
}

// ---------------------------------------------------------------
// Grid kernel: A = S/max(c,1); agg = A@mm_w2 + [c>0]*mm_b2; out = MLP_update(agg)
// ---------------------------------------------------------------
__global__ void __launch_bounds__(512, 1) grid_kernel(
    const float* __restrict__ w1, const float* __restrict__ b1g,
    const float* __restrict__ w2, const float* __restrict__ b2g,
    const float* __restrict__ w3, const float* __restrict__ b3g,
    float* __restrict__ out, int Grows)
{
    extern __shared__ float sh[];
    float* W1 = sh;
    float* W2 = sh + 16384;
    float* W3 = sh + 32768;
    float* B1 = sh + 49152;
    float* B2 = sh + 49280;
    float* B3 = sh + 49408;
    float* RS = sh + 49536;
    float* RM = sh + 49600;
    float* buf = sh + 49664;
    int t = threadIdx.x;

    for (int i = t; i < 4096; i += 512) {
        ((float4*)W1)[i] = ((const float4*)w1)[i];
        ((float4*)W2)[i] = ((const float4*)w2)[i];
        ((float4*)W3)[i] = ((const float4*)w3)[i];
    }
    if (t < 128) { B1[t] = b1g[t]; B2[t] = b2g[t]; B3[t] = b3g[t]; }
    __syncthreads();

    const int ntiles = Grows >> 6;
    const int j0 = (t & 31) << 2;
    const int r0 = (t >> 5) << 2;

    for (int tile = blockIdx.x; tile < ntiles; tile += gridDim.x) {
        const int base = tile << 6;
        if (t < 64) {
            int c = g_cnt[base + t];
            RS[t] = 1.f / (float)max(c, 1);
            RM[t] = (c > 0) ? 1.f : 0.f;
        }
        __syncthreads();
        for (int i = t; i < 2048; i += 512) {
            float4 v = ((const float4*)(g_S + (size_t)base * H))[i];
            float s = RS[i >> 5];
            v.x *= s; v.y *= s; v.z *= s; v.w *= s;
            ((float4*)buf)[i] = v;
        }
        __syncthreads();

        // layer1: A @ mm_w2 with per-row masked bias, no activation
        {
            float acc[4][4];
#pragma unroll
            for (int i = 0; i < 4; i++) {
                float m = RM[r0 + i];
#pragma unroll
                for (int c = 0; c < 4; c++) acc[i][c] = m * B1[j0 + c];
            }
#pragma unroll 8
            for (int k = 0; k < H; k++) {
                float4 w = *(const float4*)(W1 + k * H + j0);
                float x0 = buf[(r0 + 0) * H + k];
                float x1 = buf[(r0 + 1) * H + k];
                float x2 = buf[(r0 + 2) * H + k];
                float x3 = buf[(r0 + 3) * H + k];
                acc[0][0] += x0 * w.x; acc[0][1] += x0 * w.y; acc[0][2] += x0 * w.z; acc[0][3] += x0 * w.w;
                acc[1][0] += x1 * w.x; acc[1][1] += x1 * w.y; acc[1][2] += x1 * w.z; acc[1][3] += x1 * w.w;
                acc[2][0] += x2 * w.x; acc[2][1] += x2 * w.y; acc[2][2] += x2 * w.z; acc[2][3] += x2 * w.w;
                acc[3][0] += x3 * w.x; acc[3][1] += x3 * w.y; acc[3][2] += x3 * w.z; acc[3][3] += x3 * w.w;
            }
            __syncwarp();
#pragma unroll
            for (int i = 0; i < 4; i++) {
                float4 v = { acc[i][0], acc[i][1], acc[i][2], acc[i][3] };
                *(float4*)(buf + (r0 + i) * H + j0) = v;
            }
            __syncthreads();
        }

        tile_layer<true,  true, false>(W2, B2, buf, nullptr, t);
        tile_layer<false, true, true >(W3, B3, buf, out + (size_t)base * H, t);
        __syncthreads();
    }
}

// ---------------------------------------------------------------
extern "C" void kernel_launch(void* const* d_in, const int* in_sizes, int n_in,
                              void* d_out, int out_size)
{
    const float* node_features = (const float*)d_in[0];
    const float* node_pos = (const float*)d_in[1];
    const float* grid_pos = (const float*)d_in[2];
    const int*   eidx     = (const int*)d_in[3];
    const float* nm_w1 = (const float*)d_in[4],  *nm_b1 = (const float*)d_in[5];
    const float* nm_w2 = (const float*)d_in[6],  *nm_b2 = (const float*)d_in[7];
    const float* em_w1 = (const float*)d_in[8],  *em_b1 = (const float*)d_in[9];
    const float* em_w2 = (const float*)d_in[10], *em_b2 = (const float*)d_in[11];
    const float* mm_w1 = (const float*)d_in[12], *mm_b1 = (const float*)d_in[13];
    const float* mm_w2 = (const float*)d_in[14], *mm_b2 = (const float*)d_in[15];
    const float* um_w1 = (const float*)d_in[16], *um_b1 = (const float*)d_in[17];
    const float* um_w2 = (const float*)d_in[18], *um_b2 = (const float*)d_in[19];
    float* out = (float*)d_out;

    const int Nn = in_sizes[0] / H;   // 65536
    const int Gg = in_sizes[2] / 3;   // 32768
    const int Ee = in_sizes[3] / 2;   // 600000

    int nSM = 148;
    cudaDeviceGetAttribute(&nSM, cudaDevAttrMultiProcessorCount, 0);

    void *pS = nullptr, *pC = nullptr, *pM = nullptr;
    cudaGetSymbolAddress(&pS, g_S);
    cudaGetSymbolAddress(&pC, g_cnt);
    cudaGetSymbolAddress(&pM, g_max_src);
    cudaMemsetAsync(pS, 0, (size_t)Gg * H * sizeof(float));
    cudaMemsetAsync(pC, 0, (size_t)Gg * sizeof(int));
    cudaMemsetAsync(pM, 0, sizeof(int));

    probe_kernel<<<256, 256>>>(eidx, Ee);
    prep_kernel<<<129, 128>>>(em_w2, em_b2, mm_w1, mm_b1);

    cudaFuncSetAttribute(node_kernel, cudaFuncAttributeMaxDynamicSharedMemorySize, 230400);
    cudaFuncSetAttribute(edge_kernel, cudaFuncAttributeMaxDynamicSharedMemorySize, 104448);
    cudaFuncSetAttribute(grid_kernel, cudaFuncAttributeMaxDynamicSharedMemorySize, 231424);

    node_kernel<<<nSM, 512, 230400>>>(node_features, nm_w1, nm_b1, nm_w2, nm_b2, mm_w1, Nn);

    int etiles = (Ee + 63) >> 6;
    int egrid = 2 * nSM; if (egrid > etiles) egrid = etiles;
    edge_kernel<<<egrid, 256, 104448>>>(eidx, node_pos, grid_pos, em_w1, em_b1, Ee);

    grid_kernel<<<nSM, 512, 231424>>>(mm_w2, mm_b2, um_w1, um_b1, um_w2, um_b2, out, Gg);
}

// round 15
// speedup vs baseline: 1.4847x; 1.0647x over previous
#include <cuda_runtime.h>
#include <cstdint>

#define H 128
#define MAXN 65536
#define MAXG 32768

// ---------------- device scratch (no allocs allowed) ----------------
__device__ float g_z[(size_t)MAXN * H];    // z = nf @ mm_w1_top   [N,128]
__device__ float g_S[(size_t)MAXG * H];    // sum of silu(pre)     [G,128]
__device__ int   g_cnt[MAXG];              // edges per target
__device__ float g_Wp[H * H];              // W' = em_w2 @ mm_w1_bot
__device__ float g_bpp[H];                 // b'' = mm_b1 + em_b2 @ mm_w1_bot
__device__ int   g_is64;                   // edge_index dtype flag
__device__ int   g_max_src;                // max src index (limits node MLP rows)

// silu via single-MUFU tanh.approx: silu(x) = 0.5x*tanh(0.5x) + 0.5x
__device__ __forceinline__ float silu_f(float x) {
    float hx = 0.5f * x, t;
    asm("tanh.approx.f32 %0, %1;" : "=f"(t) : "f"(hx));
    return fmaf(hx, t, hx);
}

// ---------------------------------------------------------------
// Generic fused layer on a 64x128 tile held in shared memory.
// 512 threads: cols j0=(t&31)*4, warp rg=t>>5 owns rows rg*4..rg*4+3.
// ---------------------------------------------------------------
template<bool ACT, bool HASBIAS, bool TOGLOBAL>
__device__ __forceinline__ void tile_layer(const float* __restrict__ W,
                                           const float* __restrict__ b,
                                           float* __restrict__ buf,
                                           float* __restrict__ gout, int t)
{
    const int j0 = (t & 31) << 2;
    const int r0 = (t >> 5) << 2;
    float acc[4][4];
#pragma unroll
    for (int i = 0; i < 4; i++)
#pragma unroll
        for (int c = 0; c < 4; c++)
            acc[i][c] = HASBIAS ? b[j0 + c] : 0.f;

#pragma unroll 8
    for (int k = 0; k < H; k++) {
        float4 w = *(const float4*)(W + k * H + j0);
        float x0 = buf[(r0 + 0) * H + k];
        float x1 = buf[(r0 + 1) * H + k];
        float x2 = buf[(r0 + 2) * H + k];
        float x3 = buf[(r0 + 3) * H + k];
        acc[0][0] += x0 * w.x; acc[0][1] += x0 * w.y; acc[0][2] += x0 * w.z; acc[0][3] += x0 * w.w;
        acc[1][0] += x1 * w.x; acc[1][1] += x1 * w.y; acc[1][2] += x1 * w.z; acc[1][3] += x1 * w.w;
        acc[2][0] += x2 * w.x; acc[2][1] += x2 * w.y; acc[2][2] += x2 * w.z; acc[2][3] += x2 * w.w;
        acc[3][0] += x3 * w.x; acc[3][1] += x3 * w.y; acc[3][2] += x3 * w.z; acc[3][3] += x3 * w.w;
    }

    if (TOGLOBAL) {
#pragma unroll
        for (int i = 0; i < 4; i++) {
            float4 v;
            v.x = ACT ? silu_f(acc[i][0]) : acc[i][0];
            v.y = ACT ? silu_f(acc[i][1]) : acc[i][1];
            v.z = ACT ? silu_f(acc[i][2]) : acc[i][2];
            v.w = ACT ? silu_f(acc[i][3]) : acc[i][3];
            *(float4*)(gout + (size_t)(r0 + i) * H + j0) = v;
        }
    } else {
        __syncwarp();
#pragma unroll
        for (int i = 0; i < 4; i++) {
            float4 v;
            v.x = ACT ? silu_f(acc[i][0]) : acc[i][0];
            v.y = ACT ? silu_f(acc[i][1]) : acc[i][1];
            v.z = ACT ? silu_f(acc[i][2]) : acc[i][2];
            v.w = ACT ? silu_f(acc[i][3]) : acc[i][3];
            *(float4*)(buf + (r0 + i) * H + j0) = v;
        }
        __syncthreads();
    }
}

// ---------------------------------------------------------------
// Probe: detect int64 vs int32 edge_index, and max(src).
// ---------------------------------------------------------------
__global__ void probe_kernel(const int* __restrict__ ei, int E)
{
    int is64 = 1;
#pragma unroll 1
    for (int i = 0; i < 64; i++)
        if (ei[2 * i + 1] != 0) { is64 = 0; break; }
    if (blockIdx.x == 0 && threadIdx.x == 0) g_is64 = is64;

    int tid = blockIdx.x * blockDim.x + threadIdx.x;
    int stride = gridDim.x * blockDim.x;
    int m = 0;
    for (int e = tid; e < E; e += stride) {
        int s = is64 ? ei[2 * (size_t)e] : ei[e];
        m = max(m, s);
    }
#pragma unroll
    for (int o = 16; o > 0; o >>= 1) m = max(m, __shfl_xor_sync(0xffffffffu, m, o));
    if ((threadIdx.x & 31) == 0) atomicMax(&g_max_src, m);
}

// ---------------------------------------------------------------
// Precompute W' = em_w2 @ mm_w1[128:,:]  and  b'' = mm_b1 + em_b2 @ mm_w1[128:,:]
// ---------------------------------------------------------------
__global__ void prep_kernel(const float* __restrict__ emw2,
                            const float* __restrict__ emb2,
                            const float* __restrict__ mmw1,
                            const float* __restrict__ mmb1)
{
    int j = threadIdx.x;
    if (blockIdx.x < 128) {
        int a = blockIdx.x;
        float s = 0.f;
        for (int bb = 0; bb < 128; bb++)
            s += emw2[a * 128 + bb] * mmw1[(128 + bb) * 128 + j];
        g_Wp[a * 128 + j] = s;
    } else {
        float s = mmb1[j];
        for (int bb = 0; bb < 128; bb++)
            s += emb2[bb] * mmw1[(128 + bb) * 128 + j];
        g_bpp[j] = s;
    }
}

// ---------------------------------------------------------------
// Node kernel: z = (MLP_node(x)) @ mm_w1_top for rows 0..max_src
// ---------------------------------------------------------------
__global__ void __launch_bounds__(512, 1) node_kernel(
    const float* __restrict__ x,
    const float* __restrict__ w1, const float* __restrict__ b1g,
    const float* __restrict__ w2, const float* __restrict__ b2g,
    const float* __restrict__ w3, int Nrows)
{
    extern __shared__ float sh[];
    float* W1 = sh;
    float* W2 = sh + 16384;
    float* W3 = sh + 32768;
    float* B1 = sh + 49152;
    float* B2 = sh + 49280;
    float* buf = sh + 49408;
    int t = threadIdx.x;

    for (int i = t; i < 4096; i += 512) {
        ((float4*)W1)[i] = ((const float4*)w1)[i];
        ((float4*)W2)[i] = ((const float4*)w2)[i];
        ((float4*)W3)[i] = ((const float4*)w3)[i];
    }
    if (t < 128) { B1[t] = b1g[t]; B2[t] = b2g[t]; }
    __syncthreads();

    const int maxrow = g_max_src;
    const int ntiles = Nrows >> 6;
    for (int tile = blockIdx.x; tile < ntiles; tile += gridDim.x) {
        if ((tile << 6) > maxrow) continue;   // uniform across block
        const float4* xg = (const float4*)(x + (size_t)tile * 64 * H);
        for (int i = t; i < 2048; i += 512) ((float4*)buf)[i] = xg[i];
        __syncthreads();
        tile_layer<true,  true,  false>(W1, B1, buf, nullptr, t);
        tile_layer<false, true,  false>(W2, B2, buf, nullptr, t);
        tile_layer<false, false, true >(W3, nullptr, buf,
                                        g_z + (size_t)tile * 64 * H, t);
        __syncthreads();
    }
}

// ---------------------------------------------------------------
// Edge kernel v3: 64 edges/tile, 256 threads, acc[8][4] per thread.
// vs v2.1: tanh-silu (1 MUFU), z prefetched into registers at tile start
// (consumed after the GEMM -> L2 latency fully hidden), cnt atomic early.
// smem floats: Wp 16384 | hT 8192 | EW1 768 | EB1 128 | BPP 128
//              attr 384 | ssrc 64 | stgt 64  = 26112 f = 104448 B -> 2 blocks/SM
// ---------------------------------------------------------------
__global__ void __launch_bounds__(256, 2) edge_kernel(
    const int* __restrict__ ei,
    const float* __restrict__ node_pos,
    const float* __restrict__ grid_pos,
    const float* __restrict__ ew1g,
    const float* __restrict__ eb1g,
    int E)
{
    extern __shared__ float sh[];
    float* Wp   = sh;                   // 16384
    float* hT   = sh + 16384;           // 8192: [k][64 rows]
    float* EW1  = sh + 24576;           // 768
    float* EB1  = sh + 25344;           // 128
    float* BPP  = sh + 25472;           // 128
    float* attr = sh + 25600;           // 384
    int*   ssrc = (int*)(sh + 25984);   // 64
    int*   stgt = (int*)(sh + 26048);   // 64
    int t = threadIdx.x;

    for (int i = t; i < 4096; i += 256) ((float4*)Wp)[i] = ((const float4*)g_Wp)[i];
    for (int i = t; i < 768; i += 256) EW1[i] = ew1g[i];
    if (t < 128) { EB1[t] = eb1g[t]; BPP[t] = g_bpp[t]; }
    __syncthreads();

    const int is64 = g_is64;
    const int ntiles = (E + 63) >> 6;
    const int j0 = (t & 31) << 2;       // 4 output cols
    const int r0 = (t >> 5) << 3;       // 8 rows per warp
    const int hr = t & 63;              // h-phase row
    const int hkb = (t >> 6) << 5;      // h-phase col base (32 cols)

    for (int tile = blockIdx.x; tile < ntiles; tile += gridDim.x) {
        const int e0 = tile << 6;
        if (t < 128) {
            int r = t & 63;
            int e = e0 + r; if (e >= E) e = E - 1;
            if (t < 64) ssrc[r] = is64 ? ei[2 * (size_t)e] : ei[e];
            else        stgt[r] = is64 ? ei[2 * ((size_t)E + e)] : ei[(size_t)E + e];
        }
        __syncthreads();

        // z prefetch into registers (consumed after GEMM -> latency hidden)
        float4 zr[8];
#pragma unroll
        for (int i = 0; i < 8; i++)
            zr[i] = *(const float4*)(g_z + (size_t)ssrc[r0 + i] * H + j0);

        // counts early (overlaps with attr/h phases)
        if (t < 64 && (e0 + t) < E) atomicAdd(&g_cnt[stgt[t]], 1);

        // attr fill (384 entries, 256 threads)
        for (int i = t; i < 384; i += 256) {
            int r = i / 6, k = i - r * 6;
            attr[i] = (k < 3) ? node_pos[(size_t)ssrc[r] * 3 + k]
                              : grid_pos[(size_t)stgt[r] * 3 + (k - 3)];
        }
        __syncthreads();

        // h_e = silu(attr @ em_w1 + em_b1), stored transposed: hT[k][row]
        {
            float a0 = attr[hr * 6 + 0], a1 = attr[hr * 6 + 1], a2 = attr[hr * 6 + 2];
            float a3 = attr[hr * 6 + 3], a4 = attr[hr * 6 + 4], a5 = attr[hr * 6 + 5];
#pragma unroll 8
            for (int i = 0; i < 32; i++) {
                int k = hkb + i;
                float v = EB1[k]
                        + a0 * EW1[0 * H + k] + a1 * EW1[1 * H + k] + a2 * EW1[2 * H + k]
                        + a3 * EW1[3 * H + k] + a4 * EW1[4 * H + k] + a5 * EW1[5 * H + k];
                hT[k * 64 + hr] = silu_f(v);
            }
        }
        __syncthreads();

        // pre = b'' + h_e @ W'   (z added after the GEMM)
        float acc[8][4];
        {
            float b0 = BPP[j0], b1 = BPP[j0 + 1], b2 = BPP[j0 + 2], b3 = BPP[j0 + 3];
#pragma unroll
            for (int i = 0; i < 8; i++) {
                acc[i][0] = b0; acc[i][1] = b1; acc[i][2] = b2; acc[i][3] = b3;
            }
        }
#pragma unroll 8
        for (int k = 0; k < H; k++) {
            float4 w  = *(const float4*)(Wp + k * H + j0);
            float4 xa = *(const float4*)(hT + k * 64 + r0);       // rows r0..r0+3 (broadcast)
            float4 xb = *(const float4*)(hT + k * 64 + r0 + 4);   // rows r0+4..r0+7
            acc[0][0] += xa.x * w.x; acc[0][1] += xa.x * w.y; acc[0][2] += xa.x * w.z; acc[0][3] += xa.x * w.w;
            acc[1][0] += xa.y * w.x; acc[1][1] += xa.y * w.y; acc[1][2] += xa.y * w.z; acc[1][3] += xa.y * w.w;
            acc[2][0] += xa.z * w.x; acc[2][1] += xa.z * w.y; acc[2][2] += xa.z * w.z; acc[2][3] += xa.z * w.w;
            acc[3][0] += xa.w * w.x; acc[3][1] += xa.w * w.y; acc[3][2] += xa.w * w.z; acc[3][3] += xa.w * w.w;
            acc[4][0] += xb.x * w.x; acc[4][1] += xb.x * w.y; acc[4][2] += xb.x * w.z; acc[4][3] += xb.x * w.w;
            acc[5][0] += xb.y * w.x; acc[5][1] += xb.y * w.y; acc[5][2] += xb.y * w.z; acc[5][3] += xb.y * w.w;
            acc[6][0] += xb.z * w.x; acc[6][1] += xb.z * w.y; acc[6][2] += xb.z * w.z; acc[6][3] += xb.z * w.w;
            acc[7][0] += xb.w * w.x; acc[7][1] += xb.w * w.y; acc[7][2] += xb.w * w.z; acc[7][3] += xb.w * w.w;
        }

        // add prefetched z, silu, scatter with vector reductions
#pragma unroll
        for (int i = 0; i < 8; i++) {
            int e = e0 + r0 + i;
            if (e < E) {
                float a = silu_f(acc[i][0] + zr[i].x);
                float b = silu_f(acc[i][1] + zr[i].y);
                float c = silu_f(acc[i][2] + zr[i].z);
                float d = silu_f(acc[i][3] + zr[i].w);
                float* p = g_S + (size_t)stgt[r0 + i] * H + j0;
                asm volatile("red.global.add.v4.f32 [%0], {%1,%2,%3,%4};"
                             :: "l"(p), "f"(a), "f"(b), "f"(c), "f"(d) : "memory");
            }
        }
        __syncthreads();
    }
}

// ---------------------------------------------------------------
// Grid kernel: A = S/max(c,1); agg = A@mm_w2 + [c>0]*mm_b2; out = MLP_update(agg)
// ---------------------------------------------------------------
__global__ void __launch_bounds__(512, 1) grid_kernel(
    const float* __restrict__ w1, const float* __restrict__ b1g,
    const float* __restrict__ w2, const float* __restrict__ b2g,
    const float* __restrict__ w3, const float* __restrict__ b3g,
    float* __restrict__ out, int Grows)
{
    extern __shared__ float sh[];
    float* W1 = sh;
    float* W2 = sh + 16384;
    float* W3 = sh + 32768;
    float* B1 = sh + 49152;
    float* B2 = sh + 49280;
    float* B3 = sh + 49408;
    float* RS = sh + 49536;
    float* RM = sh + 49600;
    float* buf = sh + 49664;
    int t = threadIdx.x;

    for (int i = t; i < 4096; i += 512) {
        ((float4*)W1)[i] = ((const float4*)w1)[i];
        ((float4*)W2)[i] = ((const float4*)w2)[i];
        ((float4*)W3)[i] = ((const float4*)w3)[i];
    }
    if (t < 128) { B1[t] = b1g[t]; B2[t] = b2g[t]; B3[t] = b3g[t]; }
    __syncthreads();

    const int ntiles = Grows >> 6;
    const int j0 = (t & 31) << 2;
    const int r0 = (t >> 5) << 2;

    for (int tile = blockIdx.x; tile < ntiles; tile += gridDim.x) {
        const int base = tile << 6;
        if (t < 64) {
            int c = g_cnt[base + t];
            RS[t] = 1.f / (float)max(c, 1);
            RM[t] = (c > 0) ? 1.f : 0.f;
        }
        __syncthreads();
        for (int i = t; i < 2048; i += 512) {
            float4 v = ((const float4*)(g_S + (size_t)base * H))[i];
            float s = RS[i >> 5];
            v.x *= s; v.y *= s; v.z *= s; v.w *= s;
            ((float4*)buf)[i] = v;
        }
        __syncthreads();

        // layer1: A @ mm_w2 with per-row masked bias, no activation
        {
            float acc[4][4];
#pragma unroll
            for (int i = 0; i < 4; i++) {
                float m = RM[r0 + i];
#pragma unroll
                for (int c = 0; c < 4; c++) acc[i][c] = m * B1[j0 + c];
            }
#pragma unroll 8
            for (int k = 0; k < H; k++) {
                float4 w = *(const float4*)(W1 + k * H + j0);
                float x0 = buf[(r0 + 0) * H + k];
                float x1 = buf[(r0 + 1) * H + k];
                float x2 = buf[(r0 + 2) * H + k];
                float x3 = buf[(r0 + 3) * H + k];
                acc[0][0] += x0 * w.x; acc[0][1] += x0 * w.y; acc[0][2] += x0 * w.z; acc[0][3] += x0 * w.w;
                acc[1][0] += x1 * w.x; acc[1][1] += x1 * w.y; acc[1][2] += x1 * w.z; acc[1][3] += x1 * w.w;
                acc[2][0] += x2 * w.x; acc[2][1] += x2 * w.y; acc[2][2] += x2 * w.z; acc[2][3] += x2 * w.w;
                acc[3][0] += x3 * w.x; acc[3][1] += x3 * w.y; acc[3][2] += x3 * w.z; acc[3][3] += x3 * w.w;
            }
            __syncwarp();
#pragma unroll
            for (int i = 0; i < 4; i++) {
                float4 v = { acc[i][0], acc[i][1], acc[i][2], acc[i][3] };
                *(float4*)(buf + (r0 + i) * H + j0) = v;
            }
            __syncthreads();
        }

        tile_layer<true,  true, false>(W2, B2, buf, nullptr, t);
        tile_layer<false, true, true >(W3, B3, buf, out + (size_t)base * H, t);
        __syncthreads();
    }
}

// ---------------------------------------------------------------
extern "C" void kernel_launch(void* const* d_in, const int* in_sizes, int n_in,
                              void* d_out, int out_size)
{
    const float* node_features = (const float*)d_in[0];
    const float* node_pos = (const float*)d_in[1];
    const float* grid_pos = (const float*)d_in[2];
    const int*   eidx     = (const int*)d_in[3];
    const float* nm_w1 = (const float*)d_in[4],  *nm_b1 = (const float*)d_in[5];
    const float* nm_w2 = (const float*)d_in[6],  *nm_b2 = (const float*)d_in[7];
    const float* em_w1 = (const float*)d_in[8],  *em_b1 = (const float*)d_in[9];
    const float* em_w2 = (const float*)d_in[10], *em_b2 = (const float*)d_in[11];
    const float* mm_w1 = (const float*)d_in[12], *mm_b1 = (const float*)d_in[13];
    const float* mm_w2 = (const float*)d_in[14], *mm_b2 = (const float*)d_in[15];
    const float* um_w1 = (const float*)d_in[16], *um_b1 = (const float*)d_in[17];
    const float* um_w2 = (const float*)d_in[18], *um_b2 = (const float*)d_in[19];
    float* out = (float*)d_out;

    const int Nn = in_sizes[0] / H;   // 65536
    const int Gg = in_sizes[2] / 3;   // 32768
    const int Ee = in_sizes[3] / 2;   // 600000

    int nSM = 148;
    cudaDeviceGetAttribute(&nSM, cudaDevAttrMultiProcessorCount, 0);

    void *pS = nullptr, *pC = nullptr, *pM = nullptr;
    cudaGetSymbolAddress(&pS, g_S);
    cudaGetSymbolAddress(&pC, g_cnt);
    cudaGetSymbolAddress(&pM, g_max_src);
    cudaMemsetAsync(pS, 0, (size_t)Gg * H * sizeof(float));
    cudaMemsetAsync(pC, 0, (size_t)Gg * sizeof(int));
    cudaMemsetAsync(pM, 0, sizeof(int));

    probe_kernel<<<256, 256>>>(eidx, Ee);
    prep_kernel<<<129, 128>>>(em_w2, em_b2, mm_w1, mm_b1);

    cudaFuncSetAttribute(node_kernel, cudaFuncAttributeMaxDynamicSharedMemorySize, 230400);
    cudaFuncSetAttribute(edge_kernel, cudaFuncAttributeMaxDynamicSharedMemorySize, 104448);
    cudaFuncSetAttribute(grid_kernel, cudaFuncAttributeMaxDynamicSharedMemorySize, 231424);

    node_kernel<<<nSM, 512, 230400>>>(node_features, nm_w1, nm_b1, nm_w2, nm_b2, mm_w1, Nn);

    int etiles = (Ee + 63) >> 6;
    int egrid = 2 * nSM; if (egrid > etiles) egrid = etiles;
    edge_kernel<<<egrid, 256, 104448>>>(eidx, node_pos, grid_pos, em_w1, em_b1, Ee);

    grid_kernel<<<nSM, 512, 231424>>>(mm_w2, mm_b2, um_w1, um_b1, um_w2, um_b2, out, Gg);
}

// round 17
// speedup vs baseline: 2.0073x; 1.3520x over previous
#include <cuda_runtime.h>
#include <cstdint>

#define H 128
#define MAXN 65536
#define MAXG 32768

// ---------------- device scratch (no allocs allowed) ----------------
__device__ float g_z[(size_t)MAXN * H];    // z = nf @ mm_w1_top   [N,128]
__device__ float g_S[(size_t)MAXG * H];    // sum of silu(pre)     [G,128]
__device__ int   g_cnt[MAXG];              // edges per target
__device__ float g_Wp[H * H];              // W' = em_w2 @ mm_w1_bot
__device__ float g_WpF[H * H];             // W' permuted to tf32 B-fragment layout
__device__ float g_bpp[H];                 // b'' = mm_b1 + em_b2 @ mm_w1_bot
__device__ int   g_is64;                   // edge_index dtype flag
__device__ int   g_max_src;                // max src index (limits node MLP rows)

// silu via single-MUFU tanh.approx: silu(x) = 0.5x*tanh(0.5x) + 0.5x
__device__ __forceinline__ float silu_f(float x) {
    float hx = 0.5f * x, t;
    asm("tanh.approx.f32 %0, %1;" : "=f"(t) : "f"(hx));
    return fmaf(hx, t, hx);
}

__device__ __forceinline__ uint32_t to_tf32(float v) {
    uint32_t r;
    asm("cvt.rna.tf32.f32 %0, %1;" : "=r"(r) : "f"(v));
    return r;
}

// ---------------------------------------------------------------
// Generic fused layer on a 64x128 tile held in shared memory.
// 512 threads: cols j0=(t&31)*4, warp rg=t>>5 owns rows rg*4..rg*4+3.
// ---------------------------------------------------------------
template<bool ACT, bool HASBIAS, bool TOGLOBAL>
__device__ __forceinline__ void tile_layer(const float* __restrict__ W,
                                           const float* __restrict__ b,
                                           float* __restrict__ buf,
                                           float* __restrict__ gout, int t)
{
    const int j0 = (t & 31) << 2;
    const int r0 = (t >> 5) << 2;
    float acc[4][4];
#pragma unroll
    for (int i = 0; i < 4; i++)
#pragma unroll
        for (int c = 0; c < 4; c++)
            acc[i][c] = HASBIAS ? b[j0 + c] : 0.f;

#pragma unroll 8
    for (int k = 0; k < H; k++) {
        float4 w = *(const float4*)(W + k * H + j0);
        float x0 = buf[(r0 + 0) * H + k];
        float x1 = buf[(r0 + 1) * H + k];
        float x2 = buf[(r0 + 2) * H + k];
        float x3 = buf[(r0 + 3) * H + k];
        acc[0][0] += x0 * w.x; acc[0][1] += x0 * w.y; acc[0][2] += x0 * w.z; acc[0][3] += x0 * w.w;
        acc[1][0] += x1 * w.x; acc[1][1] += x1 * w.y; acc[1][2] += x1 * w.z; acc[1][3] += x1 * w.w;
        acc[2][0] += x2 * w.x; acc[2][1] += x2 * w.y; acc[2][2] += x2 * w.z; acc[2][3] += x2 * w.w;
        acc[3][0] += x3 * w.x; acc[3][1] += x3 * w.y; acc[3][2] += x3 * w.z; acc[3][3] += x3 * w.w;
    }

    if (TOGLOBAL) {
#pragma unroll
        for (int i = 0; i < 4; i++) {
            float4 v;
            v.x = ACT ? silu_f(acc[i][0]) : acc[i][0];
            v.y = ACT ? silu_f(acc[i][1]) : acc[i][1];
            v.z = ACT ? silu_f(acc[i][2]) : acc[i][2];
            v.w = ACT ? silu_f(acc[i][3]) : acc[i][3];
            *(float4*)(gout + (size_t)(r0 + i) * H + j0) = v;
        }
    } else {
        __syncwarp();
#pragma unroll
        for (int i = 0; i < 4; i++) {
            float4 v;
            v.x = ACT ? silu_f(acc[i][0]) : acc[i][0];
            v.y = ACT ? silu_f(acc[i][1]) : acc[i][1];
            v.z = ACT ? silu_f(acc[i][2]) : acc[i][2];
            v.w = ACT ? silu_f(acc[i][3]) : acc[i][3];
            *(float4*)(buf + (r0 + i) * H + j0) = v;
        }
        __syncthreads();
    }
}

// ---------------------------------------------------------------
// Probe: detect int64 vs int32 edge_index, and max(src).
// ---------------------------------------------------------------
__global__ void probe_kernel(const int* __restrict__ ei, int E)
{
    int is64 = 1;
#pragma unroll 1
    for (int i = 0; i < 64; i++)
        if (ei[2 * i + 1] != 0) { is64 = 0; break; }
    if (blockIdx.x == 0 && threadIdx.x == 0) g_is64 = is64;

    int tid = blockIdx.x * blockDim.x + threadIdx.x;
    int stride = gridDim.x * blockDim.x;
    int m = 0;
    for (int e = tid; e < E; e += stride) {
        int s = is64 ? ei[2 * (size_t)e] : ei[e];
        m = max(m, s);
    }
#pragma unroll
    for (int o = 16; o > 0; o >>= 1) m = max(m, __shfl_xor_sync(0xffffffffu, m, o));
    if ((threadIdx.x & 31) == 0) atomicMax(&g_max_src, m);
}

// ---------------------------------------------------------------
// Precompute W' = em_w2 @ mm_w1[128:,:]  and  b'' = mm_b1 + em_b2 @ mm_w1[128:,:]
// ---------------------------------------------------------------
__global__ void prep_kernel(const float* __restrict__ emw2,
                            const float* __restrict__ emb2,
                            const float* __restrict__ mmw1,
                            const float* __restrict__ mmb1)
{
    int j = threadIdx.x;
    if (blockIdx.x < 128) {
        int a = blockIdx.x;
        float s = 0.f;
        for (int bb = 0; bb < 128; bb++)
            s += emw2[a * 128 + bb] * mmw1[(128 + bb) * 128 + j];
        g_Wp[a * 128 + j] = s;
    } else {
        float s = mmb1[j];
        for (int bb = 0; bb < 128; bb++)
            s += emb2[bb] * mmw1[(128 + bb) * 128 + j];
        g_bpp[j] = s;
    }
}

// ---------------------------------------------------------------
// Permute W' into tf32 B-fragment layout for mma.m16n8k8.row.col:
//   b0 = Wp[ks*8+tid4    ][cg*64+nb*8+g]
//   b1 = Wp[ks*8+tid4 + 4][cg*64+nb*8+g]
// flat idx = ((((cg*16 + ks)*8 + nb)*32 + lane)*2 + which), lane = g*4+tid4
// ---------------------------------------------------------------
__global__ void permute_kernel()
{
    int idx = blockIdx.x * 256 + threadIdx.x;   // 0..16383
    int which = idx & 1;
    int lane  = (idx >> 1) & 31;
    int nb    = (idx >> 6) & 7;
    int ks    = (idx >> 9) & 15;
    int cg    = (idx >> 13) & 1;
    int tid4 = lane & 3, g = lane >> 2;
    int k = ks * 8 + tid4 + which * 4;
    int j = cg * 64 + nb * 8 + g;
    ((uint32_t*)g_WpF)[idx] = to_tf32(g_Wp[k * 128 + j]);
}

// ---------------------------------------------------------------
// Node kernel: z = (MLP_node(x)) @ mm_w1_top for rows 0..max_src
// ---------------------------------------------------------------
__global__ void __launch_bounds__(512, 1) node_kernel(
    const float* __restrict__ x,
    const float* __restrict__ w1, const float* __restrict__ b1g,
    const float* __restrict__ w2, const float* __restrict__ b2g,
    const float* __restrict__ w3, int Nrows)
{
    extern __shared__ float sh[];
    float* W1 = sh;
    float* W2 = sh + 16384;
    float* W3 = sh + 32768;
    float* B1 = sh + 49152;
    float* B2 = sh + 49280;
    float* buf = sh + 49408;
    int t = threadIdx.x;

    for (int i = t; i < 4096; i += 512) {
        ((float4*)W1)[i] = ((const float4*)w1)[i];
        ((float4*)W2)[i] = ((const float4*)w2)[i];
        ((float4*)W3)[i] = ((const float4*)w3)[i];
    }
    if (t < 128) { B1[t] = b1g[t]; B2[t] = b2g[t]; }
    __syncthreads();

    const int maxrow = g_max_src;
    const int ntiles = Nrows >> 6;
    for (int tile = blockIdx.x; tile < ntiles; tile += gridDim.x) {
        if ((tile << 6) > maxrow) continue;   // uniform across block
        const float4* xg = (const float4*)(x + (size_t)tile * 64 * H);
        for (int i = t; i < 2048; i += 512) ((float4*)buf)[i] = xg[i];
        __syncthreads();
        tile_layer<true,  true,  false>(W1, B1, buf, nullptr, t);
        tile_layer<false, true,  false>(W2, B2, buf, nullptr, t);
        tile_layer<false, false, true >(W3, nullptr, buf,
                                        g_z + (size_t)tile * 64 * H, t);
        __syncthreads();
    }
}

// ---------------------------------------------------------------
// Edge kernel v4 (tf32 tensor cores):
// 64 edges/tile, 256 threads = 8 warps.
// Warp w: rows rg*16..+15 (rg=w>>1), cols cg*64..+63 (cg=w&1).
// GEMM via mma.sync.m16n8k8 tf32: 16 k-steps x 8 n-blocks per warp.
// A (h) staged in fragment layout by the h-phase; B (W') preloaded in
// fragment layout from g_WpF. D -> smem (stride 132) -> existing scatter.
// smem floats: WpF 16384 | abuf 8448 | EW1 768 | EB1 128 | BPP 128
//              attr 384 | ssrc 64 | stgt 64 = 26368 f = 105472 B -> 2 blocks/SM
// ---------------------------------------------------------------
#define DSTRIDE 132

__global__ void __launch_bounds__(256, 2) edge_kernel(
    const int* __restrict__ ei,
    const float* __restrict__ node_pos,
    const float* __restrict__ grid_pos,
    const float* __restrict__ ew1g,
    const float* __restrict__ eb1g,
    int E)
{
    extern __shared__ float sh[];
    float* WpF  = sh;                   // 16384 (tf32 B fragments)
    float* abuf = sh + 16384;           // 8448: A fragments, then D buffer
    float* EW1  = sh + 24832;           // 768
    float* EB1  = sh + 25600;           // 128
    float* BPP  = sh + 25728;           // 128
    float* attr = sh + 25856;           // 384
    int*   ssrc = (int*)(sh + 26240);   // 64
    int*   stgt = (int*)(sh + 26304);   // 64
    int t = threadIdx.x;

    for (int i = t; i < 4096; i += 256) ((float4*)WpF)[i] = ((const float4*)g_WpF)[i];
    for (int i = t; i < 768; i += 256) EW1[i] = ew1g[i];
    if (t < 128) { EB1[t] = eb1g[t]; BPP[t] = g_bpp[t]; }
    __syncthreads();

    const int is64 = g_is64;
    const int ntiles = (E + 63) >> 6;

    const int lane = t & 31;
    const int w    = t >> 5;
    const int rg   = w >> 1;            // row group (16 edges)
    const int cg   = w & 1;             // col group (64 cols)
    const int g4   = lane >> 2;         // mma groupID
    const int tid4 = lane & 3;          // mma threadID_in_group

    // h-phase mapping
    const int hr  = t & 63;             // edge row
    const int hkb = (t >> 6) << 5;      // col base (32 cols)
    const int h_rg = hr >> 4, h_lr = hr & 15;
    const int h_g = h_lr & 7, h_rhalf = h_lr >> 3;
    // scatter mapping (same as v3)
    const int j0 = (t & 31) << 2;
    const int r0 = (t >> 5) << 3;

    for (int tile = blockIdx.x; tile < ntiles; tile += gridDim.x) {
        const int e0 = tile << 6;
        if (t < 128) {
            int r = t & 63;
            int e = e0 + r; if (e >= E) e = E - 1;
            if (t < 64) ssrc[r] = is64 ? ei[2 * (size_t)e] : ei[e];
            else        stgt[r] = is64 ? ei[2 * ((size_t)E + e)] : ei[(size_t)E + e];
        }
        __syncthreads();

        // z prefetch (consumed after GEMM -> latency hidden)
        float4 zr[8];
#pragma unroll
        for (int i = 0; i < 8; i++)
            zr[i] = *(const float4*)(g_z + (size_t)ssrc[r0 + i] * H + j0);

        if (t < 64 && (e0 + t) < E) atomicAdd(&g_cnt[stgt[t]], 1);

        for (int i = t; i < 384; i += 256) {
            int r = i / 6, k = i - r * 6;
            attr[i] = (k < 3) ? node_pos[(size_t)ssrc[r] * 3 + k]
                              : grid_pos[(size_t)stgt[r] * 3 + (k - 3)];
        }
        __syncthreads();

        // h-phase: h = silu(attr @ em_w1 + em_b1), written as tf32 A-fragments
        {
            float a0 = attr[hr * 6 + 0], a1 = attr[hr * 6 + 1], a2 = attr[hr * 6 + 2];
            float a3 = attr[hr * 6 + 3], a4 = attr[hr * 6 + 4], a5 = attr[hr * 6 + 5];
#pragma unroll 8
            for (int i = 0; i < 32; i++) {
                int k = hkb + i;
                float v = EB1[k]
                        + a0 * EW1[0 * H + k] + a1 * EW1[1 * H + k] + a2 * EW1[2 * H + k]
                        + a3 * EW1[3 * H + k] + a4 * EW1[4 * H + k] + a5 * EW1[5 * H + k];
                int ks = k >> 3, kin = k & 7;
                int ktid = kin & 3, khalf = kin >> 2;
                int alane = (h_g << 2) | ktid;
                int areg  = h_rhalf + (khalf << 1);
                ((uint32_t*)abuf)[(((h_rg << 4) + ks) << 7) + (alane << 2) + areg]
                    = to_tf32(silu_f(v));
            }
        }
        __syncthreads();

        // tensor-core GEMM: D[16x64 per warp] = h @ W'
        float c[8][4];
#pragma unroll
        for (int nb = 0; nb < 8; nb++) {
            c[nb][0] = 0.f; c[nb][1] = 0.f; c[nb][2] = 0.f; c[nb][3] = 0.f;
        }
#pragma unroll 2
        for (int ks = 0; ks < 16; ks++) {
            float4 af = *(const float4*)(abuf + (((rg << 4) + ks) << 7) + (lane << 2));
            uint32_t A0 = __float_as_uint(af.x), A1 = __float_as_uint(af.y);
            uint32_t A2 = __float_as_uint(af.z), A3 = __float_as_uint(af.w);
            const float* bbase = WpF + ((((cg << 4) + ks) << 3) << 6) + (lane << 1);
#pragma unroll
            for (int nb = 0; nb < 8; nb++) {
                float2 bf = *(const float2*)(bbase + (nb << 6));
                uint32_t B0 = __float_as_uint(bf.x), B1 = __float_as_uint(bf.y);
                asm volatile(
                    "mma.sync.aligned.m16n8k8.row.col.f32.tf32.tf32.f32 "
                    "{%0,%1,%2,%3}, {%4,%5,%6,%7}, {%8,%9}, {%0,%1,%2,%3};"
                    : "+f"(c[nb][0]), "+f"(c[nb][1]), "+f"(c[nb][2]), "+f"(c[nb][3])
                    : "r"(A0), "r"(A1), "r"(A2), "r"(A3), "r"(B0), "r"(B1));
            }
        }
        __syncthreads();   // all A-fragment reads done; abuf becomes D buffer

        // store C fragments to D buffer (stride 132)
        {
            int row0 = (rg << 4) + g4;
            int row1 = row0 + 8;
            int cb   = (cg << 6) + (tid4 << 1);
#pragma unroll
            for (int nb = 0; nb < 8; nb++) {
                *(float2*)(abuf + row0 * DSTRIDE + cb + (nb << 3)) = make_float2(c[nb][0], c[nb][1]);
                *(float2*)(abuf + row1 * DSTRIDE + cb + (nb << 3)) = make_float2(c[nb][2], c[nb][3]);
            }
        }
        __syncthreads();

        // scatter: pre = D + b'' + z ; silu ; red.v4
        {
            float b0 = BPP[j0], b1 = BPP[j0 + 1], b2 = BPP[j0 + 2], b3 = BPP[j0 + 3];
#pragma unroll
            for (int i = 0; i < 8; i++) {
                int e = e0 + r0 + i;
                if (e < E) {
                    const float* dr = abuf + (r0 + i) * DSTRIDE + j0;
                    float a = silu_f(dr[0] + b0 + zr[i].x);
                    float b = silu_f(dr[1] + b1 + zr[i].y);
                    float cc = silu_f(dr[2] + b2 + zr[i].z);
                    float d = silu_f(dr[3] + b3 + zr[i].w);
                    float* p = g_S + (size_t)stgt[r0 + i] * H + j0;
                    asm volatile("red.global.add.v4.f32 [%0], {%1,%2,%3,%4};"
                                 :: "l"(p), "f"(a), "f"(b), "f"(cc), "f"(d) : "memory");
                }
            }
        }
        __syncthreads();
    }
}

// ---------------------------------------------------------------
// Grid kernel: A = S/max(c,1); agg = A@mm_w2 + [c>0]*mm_b2; out = MLP_update(agg)
// ---------------------------------------------------------------
__global__ void __launch_bounds__(512, 1) grid_kernel(
    const float* __restrict__ w1, const float* __restrict__ b1g,
    const float* __restrict__ w2, const float* __restrict__ b2g,
    const float* __restrict__ w3, const float* __restrict__ b3g,
    float* __restrict__ out, int Grows)
{
    extern __shared__ float sh[];
    float* W1 = sh;
    float* W2 = sh + 16384;
    float* W3 = sh + 32768;
    float* B1 = sh + 49152;
    float* B2 = sh + 49280;
    float* B3 = sh + 49408;
    float* RS = sh + 49536;
    float* RM = sh + 49600;
    float* buf = sh + 49664;
    int t = threadIdx.x;

    for (int i = t; i < 4096; i += 512) {
        ((float4*)W1)[i] = ((const float4*)w1)[i];
        ((float4*)W2)[i] = ((const float4*)w2)[i];
        ((float4*)W3)[i] = ((const float4*)w3)[i];
    }
    if (t < 128) { B1[t] = b1g[t]; B2[t] = b2g[t]; B3[t] = b3g[t]; }
    __syncthreads();

    const int ntiles = Grows >> 6;
    const int j0 = (t & 31) << 2;
    const int r0 = (t >> 5) << 2;

    for (int tile = blockIdx.x; tile < ntiles; tile += gridDim.x) {
        const int base = tile << 6;
        if (t < 64) {
            int c = g_cnt[base + t];
            RS[t] = 1.f / (float)max(c, 1);
            RM[t] = (c > 0) ? 1.f : 0.f;
        }
        __syncthreads();
        for (int i = t; i < 2048; i += 512) {
            float4 v = ((const float4*)(g_S + (size_t)base * H))[i];
            float s = RS[i >> 5];
            v.x *= s; v.y *= s; v.z *= s; v.w *= s;
            ((float4*)buf)[i] = v;
        }
        __syncthreads();

        // layer1: A @ mm_w2 with per-row masked bias, no activation
        {
            float acc[4][4];
#pragma unroll
            for (int i = 0; i < 4; i++) {
                float m = RM[r0 + i];
#pragma unroll
                for (int c = 0; c < 4; c++) acc[i][c] = m * B1[j0 + c];
            }
#pragma unroll 8
            for (int k = 0; k < H; k++) {
                float4 w = *(const float4*)(W1 + k * H + j0);
                float x0 = buf[(r0 + 0) * H + k];
                float x1 = buf[(r0 + 1) * H + k];
                float x2 = buf[(r0 + 2) * H + k];
                float x3 = buf[(r0 + 3) * H + k];
                acc[0][0] += x0 * w.x; acc[0][1] += x0 * w.y; acc[0][2] += x0 * w.z; acc[0][3] += x0 * w.w;
                acc[1][0] += x1 * w.x; acc[1][1] += x1 * w.y; acc[1][2] += x1 * w.z; acc[1][3] += x1 * w.w;
                acc[2][0] += x2 * w.x; acc[2][1] += x2 * w.y; acc[2][2] += x2 * w.z; acc[2][3] += x2 * w.w;
                acc[3][0] += x3 * w.x; acc[3][1] += x3 * w.y; acc[3][2] += x3 * w.z; acc[3][3] += x3 * w.w;
            }
            __syncwarp();
#pragma unroll
            for (int i = 0; i < 4; i++) {
                float4 v = { acc[i][0], acc[i][1], acc[i][2], acc[i][3] };
                *(float4*)(buf + (r0 + i) * H + j0) = v;
            }
            __syncthreads();
        }

        tile_layer<true,  true, false>(W2, B2, buf, nullptr, t);
        tile_layer<false, true, true >(W3, B3, buf, out + (size_t)base * H, t);
        __syncthreads();
    }
}

// ---------------------------------------------------------------
extern "C" void kernel_launch(void* const* d_in, const int* in_sizes, int n_in,
                              void* d_out, int out_size)
{
    const float* node_features = (const float*)d_in[0];
    const float* node_pos = (const float*)d_in[1];
    const float* grid_pos = (const float*)d_in[2];
    const int*   eidx     = (const int*)d_in[3];
    const float* nm_w1 = (const float*)d_in[4],  *nm_b1 = (const float*)d_in[5];
    const float* nm_w2 = (const float*)d_in[6],  *nm_b2 = (const float*)d_in[7];
    const float* em_w1 = (const float*)d_in[8],  *em_b1 = (const float*)d_in[9];
    const float* em_w2 = (const float*)d_in[10], *em_b2 = (const float*)d_in[11];
    const float* mm_w1 = (const float*)d_in[12], *mm_b1 = (const float*)d_in[13];
    const float* mm_w2 = (const float*)d_in[14], *mm_b2 = (const float*)d_in[15];
    const float* um_w1 = (const float*)d_in[16], *um_b1 = (const float*)d_in[17];
    const float* um_w2 = (const float*)d_in[18], *um_b2 = (const float*)d_in[19];
    float* out = (float*)d_out;

    const int Nn = in_sizes[0] / H;   // 65536
    const int Gg = in_sizes[2] / 3;   // 32768
    const int Ee = in_sizes[3] / 2;   // 600000

    int nSM = 148;
    cudaDeviceGetAttribute(&nSM, cudaDevAttrMultiProcessorCount, 0);

    void *pS = nullptr, *pC = nullptr, *pM = nullptr;
    cudaGetSymbolAddress(&pS, g_S);
    cudaGetSymbolAddress(&pC, g_cnt);
    cudaGetSymbolAddress(&pM, g_max_src);
    cudaMemsetAsync(pS, 0, (size_t)Gg * H * sizeof(float));
    cudaMemsetAsync(pC, 0, (size_t)Gg * sizeof(int));
    cudaMemsetAsync(pM, 0, sizeof(int));

    probe_kernel<<<256, 256>>>(eidx, Ee);
    prep_kernel<<<129, 128>>>(em_w2, em_b2, mm_w1, mm_b1);
    permute_kernel<<<64, 256>>>();

    cudaFuncSetAttribute(node_kernel, cudaFuncAttributeMaxDynamicSharedMemorySize, 230400);
    cudaFuncSetAttribute(edge_kernel, cudaFuncAttributeMaxDynamicSharedMemorySize, 105472);
    cudaFuncSetAttribute(grid_kernel, cudaFuncAttributeMaxDynamicSharedMemorySize, 231424);

    node_kernel<<<nSM, 512, 230400>>>(node_features, nm_w1, nm_b1, nm_w2, nm_b2, mm_w1, Nn);

    int etiles = (Ee + 63) >> 6;
    int egrid = 2 * nSM; if (egrid > etiles) egrid = etiles;
    edge_kernel<<<egrid, 256, 105472>>>(eidx, node_pos, grid_pos, em_w1, em_b1, Ee);

    grid_kernel<<<nSM, 512, 231424>>>(mm_w2, mm_b2, um_w1, um_b1, um_w2, um_b2, out, Gg);
}